// round 14
// baseline (speedup 1.0000x reference)
#include <cuda_runtime.h>
#include <cuda_bf16.h>
#include <cstdint>
#include <math.h>

#define T_ 512
#define B_ 64
#define H_ 512
#define KK_ 16
#define M_ (T_*B_)       // 32768
#define NCHK 31          // 16-step chunk matrices per batch
#define LN2F 0.6931471805599453f

// ---------------- device scratch (allocation-free rule) ----------------
__device__ __nv_bfloat16 g_Xb[M_ * H_];    // 32 MB  X in bf16
__device__ __nv_bfloat16 g_W1T[H_ * H_];   // 0.5 MB W1^T in bf16
__device__ float g_em[M_ * KK_];           // 2 MB emissions (atomic-accumulated)
__device__ float g_P[B_ * NCHK * 16 * 16]; // chunk matrices, exp-form (global-max norm)
__device__ float g_R[B_ * NCHK];           // matrix log offsets
__device__ float g_Pp[B_ * 16 * 16];       // partial (tail) matrices
__device__ float g_Rp[B_];                 // partial log offsets
__device__ float g_gold[B_];

// ---------------- helpers ----------------
__device__ __forceinline__ uint32_t smem_u32(const void* p) {
    uint32_t a;
    asm("{ .reg .u64 t; cvta.to.shared.u64 t, %1; cvt.u32.u64 %0, t; }"
        : "=r"(a) : "l"(p));
    return a;
}
__device__ __forceinline__ void cp_async16(uint32_t dst, const void* src) {
    asm volatile("cp.async.cg.shared.global [%0], [%1], 16;\n" :: "r"(dst), "l"(src));
}
#define CP_COMMIT() asm volatile("cp.async.commit_group;\n" ::: "memory")
#define CP_WAIT(n)  asm volatile("cp.async.wait_group %0;\n" :: "n"(n) : "memory")

__device__ __forceinline__ void mma16816(float* d, const uint32_t* a, const uint32_t* b) {
    asm volatile(
        "mma.sync.aligned.m16n8k16.row.col.f32.bf16.bf16.f32 "
        "{%0,%1,%2,%3}, {%4,%5,%6,%7}, {%8,%9}, {%0,%1,%2,%3};\n"
        : "+f"(d[0]), "+f"(d[1]), "+f"(d[2]), "+f"(d[3])
        : "r"(a[0]), "r"(a[1]), "r"(a[2]), "r"(a[3]), "r"(b[0]), "r"(b[1]));
}
__device__ __forceinline__ void ldsm_x4(uint32_t* r, uint32_t addr) {
    asm volatile("ldmatrix.sync.aligned.m8n8.x4.shared.b16 {%0,%1,%2,%3}, [%4];\n"
                 : "=r"(r[0]), "=r"(r[1]), "=r"(r[2]), "=r"(r[3]) : "r"(addr));
}
__device__ __forceinline__ uint32_t packbf(float a, float b) {
    __nv_bfloat162 h = __floats2bfloat162_rn(a, b);
    return *(uint32_t*)&h;
}
__device__ __forceinline__ float dot16(
    const float* t, float4 b0, float4 b1, float4 b2, float4 b3)
{
    float s0 = t[0] * b0.x, s1 = t[1] * b0.y, s2 = t[2] * b0.z, s3 = t[3] * b0.w;
    s0 = fmaf(t[4],  b1.x, s0); s1 = fmaf(t[5],  b1.y, s1);
    s2 = fmaf(t[6],  b1.z, s2); s3 = fmaf(t[7],  b1.w, s3);
    s0 = fmaf(t[8],  b2.x, s0); s1 = fmaf(t[9],  b2.y, s1);
    s2 = fmaf(t[10], b2.z, s2); s3 = fmaf(t[11], b2.w, s3);
    s0 = fmaf(t[12], b3.x, s0); s1 = fmaf(t[13], b3.y, s1);
    s2 = fmaf(t[14], b3.z, s2); s3 = fmaf(t[15], b3.w, s3);
    return (s0 + s1) + (s2 + s3);
}

// ---------------------------------------------------------------------------
// Fused prep kernel (one launch)
// ---------------------------------------------------------------------------
#define PREP_CONVX   16384
#define PREP_INITEM  (PREP_CONVX + 512)
#define PREP_TOTAL   (PREP_INITEM + 256)

__global__ __launch_bounds__(256) void prep_kernel(
    const float* __restrict__ X, const float* __restrict__ W1,
    const float* __restrict__ b2, float* __restrict__ out)
{
    const int bid = blockIdx.x;
    const int tid = threadIdx.x;

    if (bid < PREP_CONVX) {
        size_t i = ((size_t)bid * 256 + tid) * 4;
        float4 v = *(const float4*)(X + i);
        uint2 u;
        u.x = packbf(v.x, v.y);
        u.y = packbf(v.z, v.w);
        *(uint2*)(g_Xb + i) = u;
    } else if (bid < PREP_INITEM) {
        if (bid == PREP_CONVX && tid == 0) out[0] = 0.f;
        size_t i = ((size_t)(bid - PREP_CONVX) * 256 + tid) * 4;
        const int ph = (int)(i & 15);
        float4 v;
        v.x = b2[ph]; v.y = b2[ph + 1]; v.z = b2[ph + 2]; v.w = b2[ph + 3];
        *(float4*)(g_em + i) = v;
    } else {
        __shared__ float t[32][33];
        const int tb = bid - PREP_INITEM;
        const int bx = (tb & 15) * 32, by = (tb >> 4) * 32;
        const int x = tid & 31, y = tid >> 5;   // 32 x 8
#pragma unroll
        for (int i = 0; i < 4; i++)
            t[y + i * 8][x] = W1[(size_t)(by + y + i * 8) * H_ + bx + x];
        __syncthreads();
#pragma unroll
        for (int i = 0; i < 4; i++)
            g_W1T[(size_t)(bx + y + i * 8) * H_ + by + x] =
                __float2bfloat16(t[x][y + i * 8]);
    }
}

// ---------------------------------------------------------------------------
// K1: fused  h = relu(X@W1+b1);  em += h @ W2   (unchanged; passing since R7)
// ---------------------------------------------------------------------------
#define BM 128
#define BN 128
#define BK 32
#define NKC (H_/BK)           // 16
#define ROWW 20
#define TILE_WORDS (BM*ROWW)
#define STAGE_WORDS (2*TILE_WORDS)
#define SMEM_BYTES (4*STAGE_WORDS*4)   // 81920

__global__ __launch_bounds__(256, 2) void gemm1_fused(
    const float* __restrict__ b1, const float* __restrict__ W2)
{
    extern __shared__ uint32_t sw[];
    const uint32_t sb = smem_u32(sw);
    const int tid  = threadIdx.x;
    const int wid  = tid >> 5, lane = tid & 31;
    const int g    = lane >> 2, t = lane & 3;
    const int wm   = wid >> 2;
    const int wn   = wid & 3;
    const int ks   = wid & 1;
    const int row0 = blockIdx.y * BM;
    const int col0 = blockIdx.x * BN;

    auto issue_stage = [&](int c, int s) {
        const int k0 = c * BK;
        const uint32_t base = (uint32_t)(s * STAGE_WORDS);
#pragma unroll
        for (int q = 0; q < 2; q++) {
            const int u   = tid + q * 256;
            const int row = u >> 2, seg = u & 3;
            cp_async16(sb + (base + row * ROWW + seg * 4) * 4,
                       g_Xb + (size_t)(row0 + row) * H_ + k0 + seg * 8);
        }
#pragma unroll
        for (int q = 0; q < 2; q++) {
            const int u   = tid + q * 256;
            const int row = u >> 2, seg = u & 3;
            cp_async16(sb + (base + TILE_WORDS + row * ROWW + seg * 4) * 4,
                       g_W1T + (size_t)(col0 + row) * H_ + k0 + seg * 8);
        }
    };

    issue_stage(0, 0); CP_COMMIT();
    issue_stage(1, 1); CP_COMMIT();
    issue_stage(2, 2); CP_COMMIT();

    const int r8    = lane & 7;
    const int aWOff = ((wm * 64 + r8 + (((lane >> 3) & 1) << 3)) * ROWW)
                    + ((lane >> 4) << 2);
    const int bWOff = TILE_WORDS
                    + ((wn * 32 + r8 + (((lane >> 4) & 1) << 3)) * ROWW)
                    + (((lane >> 3) & 1) << 2);

    float acc[4][4][4];
#pragma unroll
    for (int i = 0; i < 4; i++)
#pragma unroll
        for (int j = 0; j < 4; j++)
#pragma unroll
            for (int r = 0; r < 4; r++) acc[i][j][r] = 0.f;

    for (int c = 0; c < NKC; c++) {
        if (c <= NKC - 3)      CP_WAIT(2);
        else if (c == NKC - 2) CP_WAIT(1);
        else                   CP_WAIT(0);
        __syncthreads();
        if (c + 3 < NKC) { issue_stage(c + 3, (c + 3) & 3); CP_COMMIT(); }

        const uint32_t stg = sb + (uint32_t)(c & 3) * (STAGE_WORDS * 4);

#pragma unroll
        for (int kk2 = 0; kk2 < 2; kk2++) {
            const int kk = kk2 ^ ks;
            const int kw = kk * 8;
            uint32_t af[4][4], bf[4][2];
#pragma unroll
            for (int i = 0; i < 4; i++)
                ldsm_x4(af[i], stg + (uint32_t)(aWOff + i * 16 * ROWW + kw) * 4);
#pragma unroll
            for (int p = 0; p < 2; p++) {
                uint32_t br[4];
                ldsm_x4(br, stg + (uint32_t)(bWOff + p * 16 * ROWW + kw) * 4);
                bf[2*p][0]   = br[0]; bf[2*p][1]   = br[1];
                bf[2*p+1][0] = br[2]; bf[2*p+1][1] = br[3];
            }
#pragma unroll
            for (int i = 0; i < 4; i++)
#pragma unroll
                for (int j = 0; j < 4; j++)
                    mma16816(acc[i][j], af[i], bf[j]);
        }
    }

#pragma unroll
    for (int j = 0; j < 4; j++) {
        const int col = col0 + wn * 32 + j * 8 + 2 * t;
        const float bb0 = __ldg(b1 + col), bb1 = __ldg(b1 + col + 1);
#pragma unroll
        for (int i = 0; i < 4; i++) {
            acc[i][j][0] = fmaxf(acc[i][j][0] + bb0, 0.f);
            acc[i][j][1] = fmaxf(acc[i][j][1] + bb1, 0.f);
            acc[i][j][2] = fmaxf(acc[i][j][2] + bb0, 0.f);
            acc[i][j][3] = fmaxf(acc[i][j][3] + bb1, 0.f);
        }
    }

    uint32_t bw[2][2][2];
    {
        const int kb0 = col0 + wn * 32;
#pragma unroll
        for (int jp = 0; jp < 2; jp++)
#pragma unroll
            for (int nt = 0; nt < 2; nt++) {
                const int kb = kb0 + jp * 16;
                const int n  = nt * 8 + g;
                float w0 = __ldg(W2 + (size_t)(kb + 2*t)     * KK_ + n);
                float w1 = __ldg(W2 + (size_t)(kb + 2*t + 1) * KK_ + n);
                float w2v= __ldg(W2 + (size_t)(kb + 2*t + 8) * KK_ + n);
                float w3 = __ldg(W2 + (size_t)(kb + 2*t + 9) * KK_ + n);
                bw[jp][nt][0] = packbf(w0, w1);
                bw[jp][nt][1] = packbf(w2v, w3);
            }
    }

    __syncthreads();
    float* em_s = (float*)sw;

#pragma unroll
    for (int i = 0; i < 4; i++) {
        float e0[4] = {0.f, 0.f, 0.f, 0.f};
        float e1[4] = {0.f, 0.f, 0.f, 0.f};
#pragma unroll
        for (int jp = 0; jp < 2; jp++) {
            uint32_t af_[4];
            af_[0] = packbf(acc[i][2*jp][0],   acc[i][2*jp][1]);
            af_[1] = packbf(acc[i][2*jp][2],   acc[i][2*jp][3]);
            af_[2] = packbf(acc[i][2*jp+1][0], acc[i][2*jp+1][1]);
            af_[3] = packbf(acc[i][2*jp+1][2], acc[i][2*jp+1][3]);
            mma16816(e0, af_, bw[jp][0]);
            mma16816(e1, af_, bw[jp][1]);
        }
        const int r = wm * 64 + i * 16 + g;
        float* sl  = em_s + (size_t)(wn * 128 + r) * 18;
        float* sl8 = em_s + (size_t)(wn * 128 + r + 8) * 18;
        *(float2*)(sl  + 2*t)     = make_float2(e0[0], e0[1]);
        *(float2*)(sl  + 8 + 2*t) = make_float2(e1[0], e1[1]);
        *(float2*)(sl8 + 2*t)     = make_float2(e0[2], e0[3]);
        *(float2*)(sl8 + 8 + 2*t) = make_float2(e1[2], e1[3]);
    }
    __syncthreads();

#pragma unroll
    for (int q = 0; q < 8; q++) {
        const int o = tid + q * 256;
        const int r = o >> 4, n = o & 15;
        float s = em_s[(size_t)(0 * 128 + r) * 18 + n]
                + em_s[(size_t)(1 * 128 + r) * 18 + n]
                + em_s[(size_t)(2 * 128 + r) * 18 + n]
                + em_s[(size_t)(3 * 128 + r) * 18 + n];
        atomicAdd(g_em + (size_t)(row0 + r) * KK_ + n, s);
    }
}

// ---------------------------------------------------------------------------
// Scan phase 1: chunk matrices + tail-partial matrices + gold path.
// blockIdx.x: 0..30 = chunks, 31 = tail pseudo-chunk, 32 = gold.
// ---------------------------------------------------------------------------
__global__ __launch_bounds__(256) void scan_p1(
    const float* __restrict__ trans, const int* __restrict__ lens,
    const int* __restrict__ tags)
{
    const int c = blockIdx.x, b = blockIdx.y;
    const int tid = threadIdx.x;

    if (c == NCHK + 1) {   // ---- gold path ----
        __shared__ float wsum[8];
        const int len = lens[b];
        float v = 0.f;
#pragma unroll
        for (int h = 0; h < 2; h++) {
            const int t = tid + h * 256;
            if (t < len) {
                const int tag = tags[t * B_ + b];
                float x = g_em[(size_t)(t * B_ + b) * KK_ + tag];
                if (t > 0) x += trans[tag * KK_ + tags[(t - 1) * B_ + b]];
                v += x;
            }
        }
#pragma unroll
        for (int off = 16; off; off >>= 1)
            v += __shfl_xor_sync(0xffffffffu, v, off);
        if ((tid & 31) == 0) wsum[tid >> 5] = v;
        __syncthreads();
        if (tid == 0) {
            float s = 0.f;
#pragma unroll
            for (int i = 0; i < 8; i++) s += wsum[i];
            g_gold[b] = s;
        }
        return;
    }

    // ---- chunk chain (c <= NCHK; c == NCHK is tail-partial-only) ----
    const int last  = lens[b] - 1;
    const int nfb   = last >> 4;
    const int nrb   = last & 15;
    const bool need_partial = (c == nfb) && (nrb > 0);
    const int stash_tt = need_partial ? (nrb - 1) : -2;

    if (c == NCHK && !need_partial) return;

    const int wid  = tid >> 5, lane = tid & 31;
    const int jj   = lane & 15;
    const int col  = wid * 2 + (lane >> 4);

    __shared__ float es[16][16];
    __shared__ float cm[16][17];
    __shared__ float cmp[16][17];
    __shared__ float rms[16];
    __shared__ float rmsp[16];
    __shared__ __align__(16) float xW[2][16][16];

    {
        const int tt = tid >> 4, k = tid & 15;
        int tload = 16 * c + 1 + tt;
        if (tload > T_ - 1) tload = T_ - 1;
        es[tt][k] = g_em[(size_t)(tload * B_ + b) * KK_ + k];
    }
    float4 T0, T1, T2, T3;
    {
        float te[16];
#pragma unroll
        for (int i = 0; i < 16; i++) te[i] = __expf(trans[jj * KK_ + i]);
        T0 = make_float4(te[0], te[1], te[2], te[3]);
        T1 = make_float4(te[4], te[5], te[6], te[7]);
        T2 = make_float4(te[8], te[9], te[10], te[11]);
        T3 = make_float4(te[12], te[13], te[14], te[15]);
    }
    const float tr_own = trans[jj * KK_ + col];
    const float tr_0   = trans[col];
    __syncthreads();

    float Lbase = tr_0 + es[0][0];
    int   Lexp  = 0;
    float w_own = __expf(tr_own + es[0][jj] - Lbase);
    if (need_partial && nrb == 1)
        cmp[col][jj] = tr_own + es[0][jj];
    xW[0][col][jj] = w_own;
    __syncwarp();
    float t[16];
    {
        const float4 u0 = *(const float4*)(xW[0][col] + 0);
        const float4 u1 = *(const float4*)(xW[0][col] + 4);
        const float4 u2 = *(const float4*)(xW[0][col] + 8);
        const float4 u3 = *(const float4*)(xW[0][col] + 12);
        t[0]=u0.x; t[1]=u0.y; t[2]=u0.z; t[3]=u0.w;
        t[4]=u1.x; t[5]=u1.y; t[6]=u1.z; t[7]=u1.w;
        t[8]=u2.x; t[9]=u2.y; t[10]=u2.z; t[11]=u2.w;
        t[12]=u3.x; t[13]=u3.y; t[14]=u3.z; t[15]=u3.w;
    }
    float inv_last = 1.f;
    int pb = 1;

#pragma unroll 1
    for (int tt = 1; tt < 16; tt++) {
        const float em0 = es[tt][0];
        const float esc = __expf(es[tt][jj] - em0);
        const float w = dot16(t, T0, T1, T2, T3) * esc;
        xW[pb][col][jj] = w;
        __syncwarp();
        const float w0 = xW[pb][col][0];
        const int   e  = ((__float_as_int(w0) >> 23) & 255) - 127;
        const float inv = __int_as_float((uint32_t)(127 - e) << 23);
        Lbase += em0; Lexp += e;
        const float4 u0 = *(const float4*)(xW[pb][col] + 0);
        const float4 u1 = *(const float4*)(xW[pb][col] + 4);
        const float4 u2 = *(const float4*)(xW[pb][col] + 8);
        const float4 u3 = *(const float4*)(xW[pb][col] + 12);
        t[0]=u0.x*inv; t[1]=u0.y*inv; t[2]=u0.z*inv; t[3]=u0.w*inv;
        t[4]=u1.x*inv; t[5]=u1.y*inv; t[6]=u1.z*inv; t[7]=u1.w*inv;
        t[8]=u2.x*inv; t[9]=u2.y*inv; t[10]=u2.z*inv; t[11]=u2.w*inv;
        t[12]=u3.x*inv; t[13]=u3.y*inv; t[14]=u3.z*inv; t[15]=u3.w*inv;
        w_own = w; inv_last = inv;
        if (tt == stash_tt)
            cmp[col][jj] = Lbase + (float)Lexp * LN2F + __logf(w_own * inv_last);
        pb ^= 1;
    }
    cm[col][jj] = Lbase + (float)Lexp * LN2F + __logf(w_own * inv_last);
    __syncthreads();

    if (c < NCHK) {
        if (tid < 16) {
            float rm = cm[0][tid];
#pragma unroll
            for (int i = 1; i < 16; i++) rm = fmaxf(rm, cm[i][tid]);
            rms[tid] = rm;
        }
    }
    if (need_partial && tid < 16) {
        float rm = cmp[0][tid];
#pragma unroll
        for (int i = 1; i < 16; i++) rm = fmaxf(rm, cmp[i][tid]);
        rmsp[tid] = rm;
    }
    __syncthreads();
    if (c < NCHK && tid < 16) {
        float gmax = rms[0];
#pragma unroll
        for (int i = 1; i < 16; i++) gmax = fmaxf(gmax, rms[i]);
        float o[16];
#pragma unroll
        for (int i = 0; i < 16; i++)
            o[i] = __expf(cm[i][tid] - gmax);
        float* dst = g_P + (size_t)((b * NCHK + c) * 16 + tid) * 16;
#pragma unroll
        for (int q = 0; q < 4; q++)
            *(float4*)(dst + q * 4) =
                make_float4(o[4*q], o[4*q+1], o[4*q+2], o[4*q+3]);
        if (tid == 0) g_R[b * NCHK + c] = gmax;
    }
    if (need_partial && tid < 16) {
        float gmax = rmsp[0];
#pragma unroll
        for (int i = 1; i < 16; i++) gmax = fmaxf(gmax, rmsp[i]);
        float o[16];
#pragma unroll
        for (int i = 0; i < 16; i++)
            o[i] = __expf(cmp[i][tid] - gmax);
        float* dst = g_Pp + (size_t)(b * 16 + tid) * 16;
#pragma unroll
        for (int q = 0; q < 4; q++)
            *(float4*)(dst + q * 4) =
                make_float4(o[4*q], o[4*q+1], o[4*q+2], o[4*q+3]);
        if (tid == 0) g_Rp[b] = gmax;
    }
}

// ---------------------------------------------------------------------------
// Scan phase 2: BINARY TREE product of <=32 matrices, 5 barriers total.
// One block (256 thr) per batch; identity-padded; lazy power-of-2 renorm.
// smem layout (dynamic): M0 = 32 mats @ stride 272, MA = 16 mats @ stride 272.
// ---------------------------------------------------------------------------
#define MATW 272   // 16*17 floats per matrix slot
#define P2_SMEM ((32 + 16) * MATW * 4)   // 52224 bytes

__global__ __launch_bounds__(256) void scan_p2(
    const int* __restrict__ lens, float* __restrict__ out)
{
    extern __shared__ float smem[];
    float* const M0 = smem;              // 32 matrices
    float* const MA = smem + 32 * MATW;  // 16 matrices

    __shared__ int eA[32], eB[16];
    __shared__ float red[8];

    const int b   = blockIdx.x;
    const int tid = threadIdx.x;
    const int j = tid >> 4, i = tid & 15;
    const int last  = lens[b] - 1;
    const int nfull = last >> 4;             // 15..31
    const int nrem  = last & 15;
    const int nm    = nfull + (nrem ? 1 : 0); // 15..32

    // Lsum: all R offsets (order-independent)
    float Lsum = 0.f;
    for (int c = 0; c < nfull; c++) Lsum += g_R[b * NCHK + c];
    if (nrem) Lsum += g_Rp[b];

    // load matrices, pad with identity
    const float idv = (i == j) ? 1.f : 0.f;
#pragma unroll 1
    for (int m = 0; m < 32; m++) {
        float v;
        if (m < nfull)      v = g_P[((size_t)(b * NCHK + m) * 16 + j) * 16 + i];
        else if (m < nm)    v = g_Pp[(size_t)(b * 16 + j) * 16 + i];
        else                v = idv;
        M0[m * MATW + j * 17 + i] = v;
    }
    if (tid < 32) eA[tid] = 0;
    __syncthreads();

    // one tree level: np products, src -> dst; eSrc -> eDst
    auto level = [&](const float* src, float* dst, const int* eSrc, int* eDst,
                     int np) {
#pragma unroll 1
        for (int p = 0; p < np; p++) {
            const float* A  = src + (2 * p)     * MATW;   // earlier
            const float* Bm = src + (2 * p + 1) * MATW;   // later
            const int ea = ((__float_as_int(A[0])  >> 23) & 255) - 127;
            const int eb = ((__float_as_int(Bm[0]) >> 23) & 255) - 127;
            const float inv = __int_as_float((uint32_t)(127 - ea - eb) << 23);
            float sd = 0.f;
#pragma unroll
            for (int k = 0; k < 16; k++)
                sd = fmaf(Bm[j * 17 + k], A[k * 17 + i], sd);
            dst[p * MATW + j * 17 + i] = sd * inv;
            if (tid == 0) eDst[p] = eSrc[2 * p] + eSrc[2 * p + 1] + ea + eb;
        }
        __syncthreads();
    };

    level(M0, MA, eA, eB, 16);   // 32 -> 16
    level(MA, M0, eB, eA, 8);    // 16 -> 8
    level(M0, MA, eA, eB, 4);    // 8  -> 4
    level(MA, M0, eB, eA, 2);    // 4  -> 2
    level(M0, MA, eA, eB, 1);    // 2  -> 1  (final in MA[0], exp in eB[0])

    // epilogue: fwd = Lsum + eB[0]*ln2 + m0 + log sum_{j,i} F[j][i]*w0[i]
    const float* em = g_em + (size_t)b * KK_;
    const float m0  = em[0];
    const float w0i = __expf(em[i] - m0);
    float v = MA[j * 17 + i] * w0i;
#pragma unroll
    for (int off = 16; off; off >>= 1)
        v += __shfl_xor_sync(0xffffffffu, v, off);
    if ((tid & 31) == 0) red[tid >> 5] = v;
    __syncthreads();
    if (tid == 0) {
        float tot = 0.f;
#pragma unroll
        for (int w = 0; w < 8; w++) tot += red[w];
        const float fwd = Lsum + (float)eB[0] * LN2F + m0 + __logf(tot);
        atomicAdd(out, fwd - g_gold[b]);
    }
}

// ---------------------------------------------------------------------------
extern "C" void kernel_launch(void* const* d_in, const int* in_sizes, int n_in,
                              void* d_out, int out_size)
{
    (void)in_sizes; (void)n_in; (void)out_size;
    const float* hidden = (const float*)d_in[0];
    const float* W1     = (const float*)d_in[1];
    const float* b1     = (const float*)d_in[2];
    const float* W2     = (const float*)d_in[3];
    const float* b2     = (const float*)d_in[4];
    const float* trans  = (const float*)d_in[5];
    const int*   lens   = (const int*)d_in[6];
    const int*   tags   = (const int*)d_in[7];

    cudaFuncSetAttribute(gemm1_fused, cudaFuncAttributeMaxDynamicSharedMemorySize,
                         SMEM_BYTES);
    cudaFuncSetAttribute(scan_p2, cudaFuncAttributeMaxDynamicSharedMemorySize,
                         P2_SMEM);

    prep_kernel<<<PREP_TOTAL, 256>>>(hidden, W1, b2, (float*)d_out);
    gemm1_fused<<<dim3(H_ / BN, M_ / BM), 256, SMEM_BYTES>>>(b1, W2);
    scan_p1<<<dim3(NCHK + 2, B_), 256>>>(trans, lens, tags);
    scan_p2<<<B_, 256, P2_SMEM>>>(lens, (float*)d_out);
}

// round 15
// speedup vs baseline: 1.0553x; 1.0553x over previous
#include <cuda_runtime.h>
#include <cuda_bf16.h>
#include <cstdint>
#include <math.h>

#define T_ 512
#define B_ 64
#define H_ 512
#define KK_ 16
#define M_ (T_*B_)       // 32768
#define NCHK 31          // chunk transfer matrices per batch (chunks of 16 steps)

// ---------------- device scratch (allocation-free rule) ----------------
__device__ __nv_bfloat16 g_Xb[M_ * H_];    // 32 MB  X in bf16
__device__ __nv_bfloat16 g_W1T[H_ * H_];   // 0.5 MB W1^T in bf16
__device__ float g_em[M_ * KK_];           // 2 MB emissions (atomic-accumulated)
__device__ float g_P[B_ * NCHK * 16 * 16]; // chunk matrices, exp-form rows
__device__ float g_R[B_ * NCHK * 16];      // chunk row maxes

// ---------------- helpers ----------------
__device__ __forceinline__ uint32_t smem_u32(const void* p) {
    uint32_t a;
    asm("{ .reg .u64 t; cvta.to.shared.u64 t, %1; cvt.u32.u64 %0, t; }"
        : "=r"(a) : "l"(p));
    return a;
}
__device__ __forceinline__ void cp_async16(uint32_t dst, const void* src) {
    asm volatile("cp.async.cg.shared.global [%0], [%1], 16;\n" :: "r"(dst), "l"(src));
}
#define CP_COMMIT() asm volatile("cp.async.commit_group;\n" ::: "memory")
#define CP_WAIT(n)  asm volatile("cp.async.wait_group %0;\n" :: "n"(n) : "memory")

__device__ __forceinline__ void mma16816(float* d, const uint32_t* a, const uint32_t* b) {
    asm volatile(
        "mma.sync.aligned.m16n8k16.row.col.f32.bf16.bf16.f32 "
        "{%0,%1,%2,%3}, {%4,%5,%6,%7}, {%8,%9}, {%0,%1,%2,%3};\n"
        : "+f"(d[0]), "+f"(d[1]), "+f"(d[2]), "+f"(d[3])
        : "r"(a[0]), "r"(a[1]), "r"(a[2]), "r"(a[3]), "r"(b[0]), "r"(b[1]));
}
__device__ __forceinline__ void ldsm_x4(uint32_t* r, uint32_t addr) {
    asm volatile("ldmatrix.sync.aligned.m8n8.x4.shared.b16 {%0,%1,%2,%3}, [%4];\n"
                 : "=r"(r[0]), "=r"(r[1]), "=r"(r[2]), "=r"(r[3]) : "r"(addr));
}
__device__ __forceinline__ uint32_t packbf(float a, float b) {
    __nv_bfloat162 h = __floats2bfloat162_rn(a, b);
    return *(uint32_t*)&h;
}

// 16-wide log-semiring matvec step (smem exchange among 16 converged lanes).
__device__ __forceinline__ float lse_step(
    float alpha, int jj, float* sA, float* sEa,
    float4 P0, float4 P1, float4 P2, float4 P3)
{
    sA[jj] = alpha;
    __syncwarp(0xffffu);
    const float m  = sA[0];
    const float ea = __expf(alpha - m);
    sEa[jj] = ea;
    __syncwarp(0xffffu);
    const float4 e0 = *(const float4*)(sEa + 0);
    const float4 e1 = *(const float4*)(sEa + 4);
    const float4 e2 = *(const float4*)(sEa + 8);
    const float4 e3 = *(const float4*)(sEa + 12);
    float s0 = e0.x * P0.x, s1 = e0.y * P0.y, s2 = e0.z * P0.z, s3 = e0.w * P0.w;
    s0 = fmaf(e1.x, P1.x, s0); s1 = fmaf(e1.y, P1.y, s1);
    s2 = fmaf(e1.z, P1.z, s2); s3 = fmaf(e1.w, P1.w, s3);
    s0 = fmaf(e2.x, P2.x, s0); s1 = fmaf(e2.y, P2.y, s1);
    s2 = fmaf(e2.z, P2.z, s2); s3 = fmaf(e2.w, P2.w, s3);
    s0 = fmaf(e3.x, P3.x, s0); s1 = fmaf(e3.y, P3.y, s1);
    s2 = fmaf(e3.z, P3.z, s2); s3 = fmaf(e3.w, P3.w, s3);
    return m + __logf((s0 + s1) + (s2 + s3));
}

// ---------------------------------------------------------------------------
// Fused prep kernel (one launch)
// ---------------------------------------------------------------------------
#define PREP_CONVX   16384
#define PREP_INITEM  (PREP_CONVX + 512)
#define PREP_TOTAL   (PREP_INITEM + 256)

__global__ __launch_bounds__(256) void prep_kernel(
    const float* __restrict__ X, const float* __restrict__ W1,
    const float* __restrict__ b2, float* __restrict__ out)
{
    const int bid = blockIdx.x;
    const int tid = threadIdx.x;

    if (bid < PREP_CONVX) {
        size_t i = ((size_t)bid * 256 + tid) * 4;
        float4 v = *(const float4*)(X + i);
        uint2 u;
        u.x = packbf(v.x, v.y);
        u.y = packbf(v.z, v.w);
        *(uint2*)(g_Xb + i) = u;
    } else if (bid < PREP_INITEM) {
        if (bid == PREP_CONVX && tid == 0) out[0] = 0.f;
        size_t i = ((size_t)(bid - PREP_CONVX) * 256 + tid) * 4;
        const int ph = (int)(i & 15);
        float4 v;
        v.x = b2[ph]; v.y = b2[ph + 1]; v.z = b2[ph + 2]; v.w = b2[ph + 3];
        *(float4*)(g_em + i) = v;
    } else {
        __shared__ float t[32][33];
        const int tb = bid - PREP_INITEM;
        const int bx = (tb & 15) * 32, by = (tb >> 4) * 32;
        const int x = tid & 31, y = tid >> 5;   // 32 x 8
#pragma unroll
        for (int i = 0; i < 4; i++)
            t[y + i * 8][x] = W1[(size_t)(by + y + i * 8) * H_ + bx + x];
        __syncthreads();
#pragma unroll
        for (int i = 0; i < 4; i++)
            g_W1T[(size_t)(bx + y + i * 8) * H_ + by + x] =
                __float2bfloat16(t[x][y + i * 8]);
    }
}

// ---------------------------------------------------------------------------
// K1: fused  h = relu(X@W1+b1);  em += h @ W2
// Block 128x128, BK=32, 4-stage cp.async, 4 warps with 64x64 warp tiles
// (halves LDSM bytes/mma vs 64x32: 256 -> 192 B/mma incl. STS).
// ---------------------------------------------------------------------------
#define BM 128
#define BN 128
#define BK 32
#define NKC (H_/BK)           // 16
#define ROWW 20
#define TILE_WORDS (BM*ROWW)
#define STAGE_WORDS (2*TILE_WORDS)
#define SMEM_BYTES (4*STAGE_WORDS*4)   // 81920

__global__ __launch_bounds__(128, 2) void gemm1_fused(
    const float* __restrict__ b1, const float* __restrict__ W2)
{
    extern __shared__ uint32_t sw[];
    const uint32_t sb = smem_u32(sw);
    const int tid  = threadIdx.x;          // 0..127
    const int wid  = tid >> 5, lane = tid & 31;
    const int g    = lane >> 2, t = lane & 3;
    const int wm   = wid >> 1;             // 0..1  (row half)
    const int wn   = wid & 1;              // 0..1  (col half)
    const int ks   = wid & 1;              // kk stagger parity
    const int row0 = blockIdx.y * BM;
    const int col0 = blockIdx.x * BN;

    auto issue_stage = [&](int c, int s) {
        const int k0 = c * BK;
        const uint32_t base = (uint32_t)(s * STAGE_WORDS);
#pragma unroll
        for (int q = 0; q < 4; q++) {
            const int u   = tid + q * 128;      // 0..511 (A)
            const int row = u >> 2, seg = u & 3;
            cp_async16(sb + (base + row * ROWW + seg * 4) * 4,
                       g_Xb + (size_t)(row0 + row) * H_ + k0 + seg * 8);
        }
#pragma unroll
        for (int q = 0; q < 4; q++) {
            const int u   = tid + q * 128;      // 0..511 (B)
            const int row = u >> 2, seg = u & 3;
            cp_async16(sb + (base + TILE_WORDS + row * ROWW + seg * 4) * 4,
                       g_W1T + (size_t)(col0 + row) * H_ + k0 + seg * 8);
        }
    };

    issue_stage(0, 0); CP_COMMIT();
    issue_stage(1, 1); CP_COMMIT();
    issue_stage(2, 2); CP_COMMIT();

    // ldmatrix per-lane invariant offsets (words)
    const int r8    = lane & 7;
    const int aWOff = ((wm * 64 + r8 + (((lane >> 3) & 1) << 3)) * ROWW)
                    + ((lane >> 4) << 2);
    const int bWOff = TILE_WORDS
                    + ((wn * 64 + r8 + (((lane >> 4) & 1) << 3)) * ROWW)
                    + (((lane >> 3) & 1) << 2);

    float acc[4][8][4];
#pragma unroll
    for (int i = 0; i < 4; i++)
#pragma unroll
        for (int j = 0; j < 8; j++)
#pragma unroll
            for (int r = 0; r < 4; r++) acc[i][j][r] = 0.f;

    for (int c = 0; c < NKC; c++) {
        if (c <= NKC - 3)      CP_WAIT(2);
        else if (c == NKC - 2) CP_WAIT(1);
        else                   CP_WAIT(0);
        __syncthreads();
        if (c + 3 < NKC) { issue_stage(c + 3, (c + 3) & 3); CP_COMMIT(); }

        const uint32_t stg = sb + (uint32_t)(c & 3) * (STAGE_WORDS * 4);

#pragma unroll
        for (int kk2 = 0; kk2 < 2; kk2++) {
            const int kk = kk2 ^ ks;
            const int kw = kk * 8;
            uint32_t af[4][4], bf[8][2];
#pragma unroll
            for (int i = 0; i < 4; i++)
                ldsm_x4(af[i], stg + (uint32_t)(aWOff + i * 16 * ROWW + kw) * 4);
#pragma unroll
            for (int p = 0; p < 4; p++) {
                uint32_t br[4];
                ldsm_x4(br, stg + (uint32_t)(bWOff + p * 16 * ROWW + kw) * 4);
                bf[2*p][0]   = br[0]; bf[2*p][1]   = br[1];
                bf[2*p+1][0] = br[2]; bf[2*p+1][1] = br[3];
            }
#pragma unroll
            for (int i = 0; i < 4; i++)
#pragma unroll
                for (int j = 0; j < 8; j++)
                    mma16816(acc[i][j], af[i], bf[j]);
        }
    }

    // ---- bias + relu in registers ----
#pragma unroll
    for (int j = 0; j < 8; j++) {
        const int col = col0 + wn * 64 + j * 8 + 2 * t;
        const float bb0 = __ldg(b1 + col), bb1 = __ldg(b1 + col + 1);
#pragma unroll
        for (int i = 0; i < 4; i++) {
            acc[i][j][0] = fmaxf(acc[i][j][0] + bb0, 0.f);
            acc[i][j][1] = fmaxf(acc[i][j][1] + bb1, 0.f);
            acc[i][j][2] = fmaxf(acc[i][j][2] + bb0, 0.f);
            acc[i][j][3] = fmaxf(acc[i][j][3] + bb1, 0.f);
        }
    }

    // ---- fused em: warp's 64x64 h-tile -> 64x16 partial, 4 k16 groups ----
    uint32_t bw[4][2][2];   // [jp 0..3][ntile][reg]
    {
        const int kb0 = col0 + wn * 64;
#pragma unroll
        for (int jp = 0; jp < 4; jp++)
#pragma unroll
            for (int nt = 0; nt < 2; nt++) {
                const int kb = kb0 + jp * 16;
                const int n  = nt * 8 + g;
                float w0 = __ldg(W2 + (size_t)(kb + 2*t)     * KK_ + n);
                float w1 = __ldg(W2 + (size_t)(kb + 2*t + 1) * KK_ + n);
                float w2v= __ldg(W2 + (size_t)(kb + 2*t + 8) * KK_ + n);
                float w3 = __ldg(W2 + (size_t)(kb + 2*t + 9) * KK_ + n);
                bw[jp][nt][0] = packbf(w0, w1);
                bw[jp][nt][1] = packbf(w2v, w3);
            }
    }

    __syncthreads();
    float* em_s = (float*)sw;   // overlay: [2 wn][128 rows][18]

#pragma unroll
    for (int i = 0; i < 4; i++) {
        float e0[4] = {0.f, 0.f, 0.f, 0.f};
        float e1[4] = {0.f, 0.f, 0.f, 0.f};
#pragma unroll
        for (int jp = 0; jp < 4; jp++) {
            uint32_t af_[4];
            af_[0] = packbf(acc[i][2*jp][0],   acc[i][2*jp][1]);
            af_[1] = packbf(acc[i][2*jp][2],   acc[i][2*jp][3]);
            af_[2] = packbf(acc[i][2*jp+1][0], acc[i][2*jp+1][1]);
            af_[3] = packbf(acc[i][2*jp+1][2], acc[i][2*jp+1][3]);
            mma16816(e0, af_, bw[jp][0]);
            mma16816(e1, af_, bw[jp][1]);
        }
        const int r = wm * 64 + i * 16 + g;
        float* sl  = em_s + (size_t)(wn * 128 + r) * 18;
        float* sl8 = em_s + (size_t)(wn * 128 + r + 8) * 18;
        *(float2*)(sl  + 2*t)     = make_float2(e0[0], e0[1]);
        *(float2*)(sl  + 8 + 2*t) = make_float2(e1[0], e1[1]);
        *(float2*)(sl8 + 2*t)     = make_float2(e0[2], e0[3]);
        *(float2*)(sl8 + 8 + 2*t) = make_float2(e1[2], e1[3]);
    }
    __syncthreads();

#pragma unroll
    for (int q = 0; q < 16; q++) {
        const int o = tid + q * 128;       // 0..2047
        const int r = o >> 4, n = o & 15;
        float s = em_s[(size_t)(0 * 128 + r) * 18 + n]
                + em_s[(size_t)(1 * 128 + r) * 18 + n];
        atomicAdd(g_em + (size_t)(row0 + r) * KK_ + n, s);
    }
}

// ---------------------------------------------------------------------------
// Scan phase 1: chunk matrices (R9 version, smem-exchange chains).
// ---------------------------------------------------------------------------
__global__ __launch_bounds__(256) void scan_p1(const float* __restrict__ trans)
{
    const int c = blockIdx.x, b = blockIdx.y;
    const int tid  = threadIdx.x;
    const int wid  = tid >> 5, lane = tid & 31;
    const int jj   = lane & 15;
    const int col  = wid * 2 + (lane >> 4);

    __shared__ float es[16][16];
    __shared__ float cm[16][17];
    __shared__ __align__(16) float xA[16][16];
    __shared__ __align__(16) float xE[16][16];

    {
        const int tt = tid >> 4, k = tid & 15;
        es[tt][k] = g_em[(size_t)((16*c + 1 + tt) * B_ + b) * KK_ + k];
    }
    float4 T0, T1, T2, T3;
    {
        float te[16];
#pragma unroll
        for (int i = 0; i < 16; i++)
            te[i] = __expf(trans[jj * KK_ + i]);
        T0 = make_float4(te[0], te[1], te[2], te[3]);
        T1 = make_float4(te[4], te[5], te[6], te[7]);
        T2 = make_float4(te[8], te[9], te[10], te[11]);
        T3 = make_float4(te[12], te[13], te[14], te[15]);
    }
    const float tr_col = trans[jj * KK_ + col];
    __syncthreads();

    float v = tr_col + es[0][jj];
#pragma unroll 1
    for (int tt = 1; tt < 16; tt++) {
        // width-16 exchange within the warp halves sharing this chain
        xA[col][jj] = v;
        __syncwarp();
        const float m  = xA[col][0];
        const float ea = __expf(v - m);
        xE[col][jj] = ea;
        __syncwarp();
        const float4 e0 = *(const float4*)(xE[col] + 0);
        const float4 e1 = *(const float4*)(xE[col] + 4);
        const float4 e2 = *(const float4*)(xE[col] + 8);
        const float4 e3 = *(const float4*)(xE[col] + 12);
        float s0 = e0.x * T0.x, s1 = e0.y * T0.y, s2 = e0.z * T0.z, s3 = e0.w * T0.w;
        s0 = fmaf(e1.x, T1.x, s0); s1 = fmaf(e1.y, T1.y, s1);
        s2 = fmaf(e1.z, T1.z, s2); s3 = fmaf(e1.w, T1.w, s3);
        s0 = fmaf(e2.x, T2.x, s0); s1 = fmaf(e2.y, T2.y, s1);
        s2 = fmaf(e2.z, T2.z, s2); s3 = fmaf(e2.w, T2.w, s3);
        s0 = fmaf(e3.x, T3.x, s0); s1 = fmaf(e3.y, T3.y, s1);
        s2 = fmaf(e3.z, T3.z, s2); s3 = fmaf(e3.w, T3.w, s3);
        v = m + __logf((s0 + s1) + (s2 + s3)) + es[tt][jj];
    }
    cm[col][jj] = v;
    __syncthreads();

    if (tid < 16) {
        float r[16];
        float rm = -3.0e38f;
#pragma unroll
        for (int i = 0; i < 16; i++) {
            r[i] = cm[i][tid];
            rm = fmaxf(rm, r[i]);
        }
        float out4[16];
#pragma unroll
        for (int i = 0; i < 16; i++)
            out4[i] = __expf(r[i] - rm);
        float* dst = g_P + (size_t)((b * NCHK + c) * 16 + tid) * 16;
#pragma unroll
        for (int q = 0; q < 4; q++)
            *(float4*)(dst + q * 4) =
                make_float4(out4[4*q], out4[4*q+1], out4[4*q+2], out4[4*q+3]);
        g_R[(b * NCHK + c) * 16 + tid] = rm;
    }
}

// ---------------------------------------------------------------------------
// Scan phase 2 (R9 version): smem-exchange combine + reg P/R prefetch;
// lanes 0-15 scan; warp 1 gold path.
// ---------------------------------------------------------------------------
__global__ __launch_bounds__(64) void scan_p2(
    const float* __restrict__ trans, const int* __restrict__ lens,
    const int* __restrict__ tags, float* __restrict__ out)
{
    const int b   = blockIdx.x;
    const int tid = threadIdx.x;
    const unsigned F = 0xffffffffu;
    const int len   = lens[b];
    const int last  = len - 1;
    const int nfull = last >> 4;
    const int nrem  = last & 15;

    __shared__ float sOut[2];
    __shared__ __align__(16) float sA[16];
    __shared__ __align__(16) float sEa[16];

    if (tid < 16) {
        const int jj = tid;
        float4 T0, T1, T2, T3;
        {
            float te[16];
#pragma unroll
            for (int i = 0; i < 16; i++)
                te[i] = __expf(trans[jj * KK_ + i]);
            T0 = make_float4(te[0], te[1], te[2], te[3]);
            T1 = make_float4(te[4], te[5], te[6], te[7]);
            T2 = make_float4(te[8], te[9], te[10], te[11]);
            T3 = make_float4(te[12], te[13], te[14], te[15]);
        }

        float alpha = g_em[(size_t)(0 * B_ + b) * KK_ + jj];

        float4 Pc0, Pc1, Pc2, Pc3, Pn0, Pn1, Pn2, Pn3;
        float  Rc = 0.f, Rn = 0.f;
        {
            const float* src = g_P + ((size_t)(b * NCHK + 0) * 16 + jj) * 16;
            Pc0 = *(const float4*)(src);
            Pc1 = *(const float4*)(src + 4);
            Pc2 = *(const float4*)(src + 8);
            Pc3 = *(const float4*)(src + 12);
            Rc  = g_R[(b * NCHK + 0) * 16 + jj];
        }

        for (int c = 0; c < nfull; c++) {
            if (c + 1 < nfull) {
                const float* src = g_P + ((size_t)(b * NCHK + c + 1) * 16 + jj) * 16;
                Pn0 = *(const float4*)(src);
                Pn1 = *(const float4*)(src + 4);
                Pn2 = *(const float4*)(src + 8);
                Pn3 = *(const float4*)(src + 12);
                Rn  = g_R[(b * NCHK + c + 1) * 16 + jj];
            }
            alpha = lse_step(alpha, jj, sA, sEa, Pc0, Pc1, Pc2, Pc3) + Rc;
            Pc0 = Pn0; Pc1 = Pn1; Pc2 = Pn2; Pc3 = Pn3; Rc = Rn;
        }

        float e_cur = (nrem > 0)
            ? g_em[(size_t)((16 * nfull + 1) * B_ + b) * KK_ + jj] : 0.f;
        for (int s = 0; s < nrem; s++) {
            float e_nxt = 0.f;
            if (s + 1 < nrem)
                e_nxt = g_em[(size_t)((16 * nfull + 2 + s) * B_ + b) * KK_ + jj];
            alpha = lse_step(alpha, jj, sA, sEa, T0, T1, T2, T3) + e_cur;
            e_cur = e_nxt;
        }

        float m2 = alpha;
#pragma unroll
        for (int off = 8; off; off >>= 1)
            m2 = fmaxf(m2, __shfl_xor_sync(0xffffu, m2, off, 16));
        float ss = __expf(alpha - m2);
#pragma unroll
        for (int off = 8; off; off >>= 1)
            ss += __shfl_xor_sync(0xffffu, ss, off, 16);
        if (jj == 0) sOut[0] = m2 + __logf(ss);
    } else if (tid >= 32) {
        const int lane = tid - 32;
        float g = 0.f;
#pragma unroll
        for (int t = 0; t < 16; t++) {
            const int tt = lane + t * 32;
            if (tt < len) {
                const int tag = tags[tt * B_ + b];
                float v = g_em[(size_t)(tt * B_ + b) * KK_ + tag];
                if (tt > 0) {
                    const int tp = tags[(tt - 1) * B_ + b];
                    v += trans[tag * KK_ + tp];
                }
                g += v;
            }
        }
#pragma unroll
        for (int off = 16; off; off >>= 1)
            g += __shfl_xor_sync(F, g, off);
        if (lane == 0) sOut[1] = g;
    }
    __syncthreads();
    if (tid == 0) atomicAdd(out, sOut[0] - sOut[1]);
}

// ---------------------------------------------------------------------------
extern "C" void kernel_launch(void* const* d_in, const int* in_sizes, int n_in,
                              void* d_out, int out_size)
{
    (void)in_sizes; (void)n_in; (void)out_size;
    const float* hidden = (const float*)d_in[0];
    const float* W1     = (const float*)d_in[1];
    const float* b1     = (const float*)d_in[2];
    const float* W2     = (const float*)d_in[3];
    const float* b2     = (const float*)d_in[4];
    const float* trans  = (const float*)d_in[5];
    const int*   lens   = (const int*)d_in[6];
    const int*   tags   = (const int*)d_in[7];

    cudaFuncSetAttribute(gemm1_fused, cudaFuncAttributeMaxDynamicSharedMemorySize,
                         SMEM_BYTES);

    prep_kernel<<<PREP_TOTAL, 256>>>(hidden, W1, b2, (float*)d_out);
    gemm1_fused<<<dim3(H_ / BN, M_ / BM), 128, SMEM_BYTES>>>(b1, W2);
    scan_p1<<<dim3(NCHK, B_), 256>>>(trans);
    scan_p2<<<B_, 64>>>(trans, lens, tags, (float*)d_out);
}

// round 16
// speedup vs baseline: 1.0942x; 1.0369x over previous
#include <cuda_runtime.h>
#include <cuda_bf16.h>
#include <cstdint>
#include <math.h>

#define T_ 512
#define B_ 64
#define H_ 512
#define KK_ 16
#define M_ (T_*B_)       // 32768
#define NCHK 31
#define LN2F 0.6931471805599453f
#define MS 256           // floats per stored 16x16 matrix

// ---------------- device scratch ----------------
__device__ __nv_bfloat16 g_Xb[M_ * H_];
__device__ __nv_bfloat16 g_W1T[H_ * H_];
__device__ float g_em[M_ * KK_];
__device__ float g_P[B_ * NCHK * MS];   // chunk matrices, exp-form, scalar-gmax norm
__device__ float g_R[B_ * NCHK];        // scalar log offsets
__device__ float g_Pp[B_ * MS];         // tail partial matrices
__device__ float g_Rp[B_];

// ---------------- helpers ----------------
__device__ __forceinline__ uint32_t smem_u32(const void* p) {
    uint32_t a;
    asm("{ .reg .u64 t; cvta.to.shared.u64 t, %1; cvt.u32.u64 %0, t; }"
        : "=r"(a) : "l"(p));
    return a;
}
__device__ __forceinline__ void cp_async16(uint32_t dst, const void* src) {
    asm volatile("cp.async.cg.shared.global [%0], [%1], 16;\n" :: "r"(dst), "l"(src));
}
#define CP_COMMIT() asm volatile("cp.async.commit_group;\n" ::: "memory")
#define CP_WAIT(n)  asm volatile("cp.async.wait_group %0;\n" :: "n"(n) : "memory")

__device__ __forceinline__ void mma16816(float* d, const uint32_t* a, const uint32_t* b) {
    asm volatile(
        "mma.sync.aligned.m16n8k16.row.col.f32.bf16.bf16.f32 "
        "{%0,%1,%2,%3}, {%4,%5,%6,%7}, {%8,%9}, {%0,%1,%2,%3};\n"
        : "+f"(d[0]), "+f"(d[1]), "+f"(d[2]), "+f"(d[3])
        : "r"(a[0]), "r"(a[1]), "r"(a[2]), "r"(a[3]), "r"(b[0]), "r"(b[1]));
}
__device__ __forceinline__ void ldsm_x4(uint32_t* r, uint32_t addr) {
    asm volatile("ldmatrix.sync.aligned.m8n8.x4.shared.b16 {%0,%1,%2,%3}, [%4];\n"
                 : "=r"(r[0]), "=r"(r[1]), "=r"(r[2]), "=r"(r[3]) : "r"(addr));
}
__device__ __forceinline__ uint32_t packbf(float a, float b) {
    __nv_bfloat162 h = __floats2bfloat162_rn(a, b);
    return *(uint32_t*)&h;
}
__device__ __forceinline__ float dot16(
    const float* t, float4 b0, float4 b1, float4 b2, float4 b3)
{
    float s0 = t[0] * b0.x, s1 = t[1] * b0.y, s2 = t[2] * b0.z, s3 = t[3] * b0.w;
    s0 = fmaf(t[4],  b1.x, s0); s1 = fmaf(t[5],  b1.y, s1);
    s2 = fmaf(t[6],  b1.z, s2); s3 = fmaf(t[7],  b1.w, s3);
    s0 = fmaf(t[8],  b2.x, s0); s1 = fmaf(t[9],  b2.y, s1);
    s2 = fmaf(t[10], b2.z, s2); s3 = fmaf(t[11], b2.w, s3);
    s0 = fmaf(t[12], b3.x, s0); s1 = fmaf(t[13], b3.y, s1);
    s2 = fmaf(t[14], b3.z, s2); s3 = fmaf(t[15], b3.w, s3);
    return (s0 + s1) + (s2 + s3);
}

// ---------------------------------------------------------------------------
// Fused prep kernel (unchanged)
// ---------------------------------------------------------------------------
#define PREP_CONVX   16384
#define PREP_INITEM  (PREP_CONVX + 512)
#define PREP_TOTAL   (PREP_INITEM + 256)

__global__ __launch_bounds__(256) void prep_kernel(
    const float* __restrict__ X, const float* __restrict__ W1,
    const float* __restrict__ b2, float* __restrict__ out)
{
    const int bid = blockIdx.x;
    const int tid = threadIdx.x;

    if (bid < PREP_CONVX) {
        size_t i = ((size_t)bid * 256 + tid) * 4;
        float4 v = *(const float4*)(X + i);
        uint2 u;
        u.x = packbf(v.x, v.y);
        u.y = packbf(v.z, v.w);
        *(uint2*)(g_Xb + i) = u;
    } else if (bid < PREP_INITEM) {
        if (bid == PREP_CONVX && tid == 0) out[0] = 0.f;
        size_t i = ((size_t)(bid - PREP_CONVX) * 256 + tid) * 4;
        const int ph = (int)(i & 15);
        float4 v;
        v.x = b2[ph]; v.y = b2[ph + 1]; v.z = b2[ph + 2]; v.w = b2[ph + 3];
        *(float4*)(g_em + i) = v;
    } else {
        __shared__ float t[32][33];
        const int tb = bid - PREP_INITEM;
        const int bx = (tb & 15) * 32, by = (tb >> 4) * 32;
        const int x = tid & 31, y = tid >> 5;
#pragma unroll
        for (int i = 0; i < 4; i++)
            t[y + i * 8][x] = W1[(size_t)(by + y + i * 8) * H_ + bx + x];
        __syncthreads();
#pragma unroll
        for (int i = 0; i < 4; i++)
            g_W1T[(size_t)(bx + y + i * 8) * H_ + by + x] =
                __float2bfloat16(t[x][y + i * 8]);
    }
}

// ---------------------------------------------------------------------------
// K1: fused gemm (R15 version: 128 threads, 64x64 warp tiles)
// ---------------------------------------------------------------------------
#define BM 128
#define BN 128
#define BK 32
#define NKC (H_/BK)
#define ROWW 20
#define TILE_WORDS (BM*ROWW)
#define STAGE_WORDS (2*TILE_WORDS)
#define SMEM_BYTES (4*STAGE_WORDS*4)

__global__ __launch_bounds__(128, 2) void gemm1_fused(
    const float* __restrict__ b1, const float* __restrict__ W2)
{
    extern __shared__ uint32_t sw[];
    const uint32_t sb = smem_u32(sw);
    const int tid  = threadIdx.x;
    const int wid  = tid >> 5, lane = tid & 31;
    const int g    = lane >> 2, t = lane & 3;
    const int wm   = wid >> 1;
    const int wn   = wid & 1;
    const int ks   = wid & 1;
    const int row0 = blockIdx.y * BM;
    const int col0 = blockIdx.x * BN;

    auto issue_stage = [&](int c, int s) {
        const int k0 = c * BK;
        const uint32_t base = (uint32_t)(s * STAGE_WORDS);
#pragma unroll
        for (int q = 0; q < 4; q++) {
            const int u   = tid + q * 128;
            const int row = u >> 2, seg = u & 3;
            cp_async16(sb + (base + row * ROWW + seg * 4) * 4,
                       g_Xb + (size_t)(row0 + row) * H_ + k0 + seg * 8);
        }
#pragma unroll
        for (int q = 0; q < 4; q++) {
            const int u   = tid + q * 128;
            const int row = u >> 2, seg = u & 3;
            cp_async16(sb + (base + TILE_WORDS + row * ROWW + seg * 4) * 4,
                       g_W1T + (size_t)(col0 + row) * H_ + k0 + seg * 8);
        }
    };

    issue_stage(0, 0); CP_COMMIT();
    issue_stage(1, 1); CP_COMMIT();
    issue_stage(2, 2); CP_COMMIT();

    const int r8    = lane & 7;
    const int aWOff = ((wm * 64 + r8 + (((lane >> 3) & 1) << 3)) * ROWW)
                    + ((lane >> 4) << 2);
    const int bWOff = TILE_WORDS
                    + ((wn * 64 + r8 + (((lane >> 4) & 1) << 3)) * ROWW)
                    + (((lane >> 3) & 1) << 2);

    float acc[4][8][4];
#pragma unroll
    for (int i = 0; i < 4; i++)
#pragma unroll
        for (int j = 0; j < 8; j++)
#pragma unroll
            for (int r = 0; r < 4; r++) acc[i][j][r] = 0.f;

    for (int c = 0; c < NKC; c++) {
        if (c <= NKC - 3)      CP_WAIT(2);
        else if (c == NKC - 2) CP_WAIT(1);
        else                   CP_WAIT(0);
        __syncthreads();
        if (c + 3 < NKC) { issue_stage(c + 3, (c + 3) & 3); CP_COMMIT(); }

        const uint32_t stg = sb + (uint32_t)(c & 3) * (STAGE_WORDS * 4);

#pragma unroll
        for (int kk2 = 0; kk2 < 2; kk2++) {
            const int kk = kk2 ^ ks;
            const int kw = kk * 8;
            uint32_t af[4][4], bf[8][2];
#pragma unroll
            for (int i = 0; i < 4; i++)
                ldsm_x4(af[i], stg + (uint32_t)(aWOff + i * 16 * ROWW + kw) * 4);
#pragma unroll
            for (int p = 0; p < 4; p++) {
                uint32_t br[4];
                ldsm_x4(br, stg + (uint32_t)(bWOff + p * 16 * ROWW + kw) * 4);
                bf[2*p][0]   = br[0]; bf[2*p][1]   = br[1];
                bf[2*p+1][0] = br[2]; bf[2*p+1][1] = br[3];
            }
#pragma unroll
            for (int i = 0; i < 4; i++)
#pragma unroll
                for (int j = 0; j < 8; j++)
                    mma16816(acc[i][j], af[i], bf[j]);
        }
    }

#pragma unroll
    for (int j = 0; j < 8; j++) {
        const int col = col0 + wn * 64 + j * 8 + 2 * t;
        const float bb0 = __ldg(b1 + col), bb1 = __ldg(b1 + col + 1);
#pragma unroll
        for (int i = 0; i < 4; i++) {
            acc[i][j][0] = fmaxf(acc[i][j][0] + bb0, 0.f);
            acc[i][j][1] = fmaxf(acc[i][j][1] + bb1, 0.f);
            acc[i][j][2] = fmaxf(acc[i][j][2] + bb0, 0.f);
            acc[i][j][3] = fmaxf(acc[i][j][3] + bb1, 0.f);
        }
    }

    uint32_t bw[4][2][2];
    {
        const int kb0 = col0 + wn * 64;
#pragma unroll
        for (int jp = 0; jp < 4; jp++)
#pragma unroll
            for (int nt = 0; nt < 2; nt++) {
                const int kb = kb0 + jp * 16;
                const int n  = nt * 8 + g;
                float w0 = __ldg(W2 + (size_t)(kb + 2*t)     * KK_ + n);
                float w1 = __ldg(W2 + (size_t)(kb + 2*t + 1) * KK_ + n);
                float w2v= __ldg(W2 + (size_t)(kb + 2*t + 8) * KK_ + n);
                float w3 = __ldg(W2 + (size_t)(kb + 2*t + 9) * KK_ + n);
                bw[jp][nt][0] = packbf(w0, w1);
                bw[jp][nt][1] = packbf(w2v, w3);
            }
    }

    __syncthreads();
    float* em_s = (float*)sw;

#pragma unroll
    for (int i = 0; i < 4; i++) {
        float e0[4] = {0.f, 0.f, 0.f, 0.f};
        float e1[4] = {0.f, 0.f, 0.f, 0.f};
#pragma unroll
        for (int jp = 0; jp < 4; jp++) {
            uint32_t af_[4];
            af_[0] = packbf(acc[i][2*jp][0],   acc[i][2*jp][1]);
            af_[1] = packbf(acc[i][2*jp][2],   acc[i][2*jp][3]);
            af_[2] = packbf(acc[i][2*jp+1][0], acc[i][2*jp+1][1]);
            af_[3] = packbf(acc[i][2*jp+1][2], acc[i][2*jp+1][3]);
            mma16816(e0, af_, bw[jp][0]);
            mma16816(e1, af_, bw[jp][1]);
        }
        const int r = wm * 64 + i * 16 + g;
        float* sl  = em_s + (size_t)(wn * 128 + r) * 18;
        float* sl8 = em_s + (size_t)(wn * 128 + r + 8) * 18;
        *(float2*)(sl  + 2*t)     = make_float2(e0[0], e0[1]);
        *(float2*)(sl  + 8 + 2*t) = make_float2(e1[0], e1[1]);
        *(float2*)(sl8 + 2*t)     = make_float2(e0[2], e0[3]);
        *(float2*)(sl8 + 8 + 2*t) = make_float2(e1[2], e1[3]);
    }
    __syncthreads();

#pragma unroll
    for (int q = 0; q < 16; q++) {
        const int o = tid + q * 128;
        const int r = o >> 4, n = o & 15;
        float s = em_s[(size_t)(0 * 128 + r) * 18 + n]
                + em_s[(size_t)(1 * 128 + r) * 18 + n];
        atomicAdd(g_em + (size_t)(row0 + r) * KK_ + n, s);
    }
}

// ---------------------------------------------------------------------------
// Scan phase 1 (R13 version): chunk matrices (scalar-gmax) + tail partial.
// blockIdx.x: 0..30 chunks, 31 = pseudo-chunk (tail when nfull==31).
// ---------------------------------------------------------------------------
__global__ __launch_bounds__(256) void scan_p1(
    const float* __restrict__ trans, const int* __restrict__ lens)
{
    const int c = blockIdx.x, b = blockIdx.y;
    const int tid = threadIdx.x;

    const int last  = lens[b] - 1;
    const int nfb   = last >> 4;
    const int nrb   = last & 15;
    const bool need_partial = (c == nfb) && (nrb > 0);
    const int stash_tt = need_partial ? (nrb - 1) : -2;

    if (c == NCHK && !need_partial) return;

    const int wid  = tid >> 5, lane = tid & 31;
    const int jj   = lane & 15;
    const int col  = wid * 2 + (lane >> 4);

    __shared__ float es[16][16];
    __shared__ float cm[16][17];
    __shared__ float cmp[16][17];
    __shared__ float rms[16];
    __shared__ float rmsp[16];
    __shared__ __align__(16) float xW[2][16][16];

    {
        const int tt = tid >> 4, k = tid & 15;
        int tload = 16 * c + 1 + tt;
        if (tload > T_ - 1) tload = T_ - 1;
        es[tt][k] = g_em[(size_t)(tload * B_ + b) * KK_ + k];
    }
    float4 T0, T1, T2, T3;
    {
        float te[16];
#pragma unroll
        for (int i = 0; i < 16; i++) te[i] = __expf(trans[jj * KK_ + i]);
        T0 = make_float4(te[0], te[1], te[2], te[3]);
        T1 = make_float4(te[4], te[5], te[6], te[7]);
        T2 = make_float4(te[8], te[9], te[10], te[11]);
        T3 = make_float4(te[12], te[13], te[14], te[15]);
    }
    const float tr_own = trans[jj * KK_ + col];
    const float tr_0   = trans[col];
    __syncthreads();

    float Lbase = tr_0 + es[0][0];
    int   Lexp  = 0;
    float w_own = __expf(tr_own + es[0][jj] - Lbase);
    if (need_partial && nrb == 1)
        cmp[col][jj] = tr_own + es[0][jj];
    xW[0][col][jj] = w_own;
    __syncwarp();
    float t[16];
    {
        const float4 u0 = *(const float4*)(xW[0][col] + 0);
        const float4 u1 = *(const float4*)(xW[0][col] + 4);
        const float4 u2 = *(const float4*)(xW[0][col] + 8);
        const float4 u3 = *(const float4*)(xW[0][col] + 12);
        t[0]=u0.x; t[1]=u0.y; t[2]=u0.z; t[3]=u0.w;
        t[4]=u1.x; t[5]=u1.y; t[6]=u1.z; t[7]=u1.w;
        t[8]=u2.x; t[9]=u2.y; t[10]=u2.z; t[11]=u2.w;
        t[12]=u3.x; t[13]=u3.y; t[14]=u3.z; t[15]=u3.w;
    }
    float inv_last = 1.f;
    int pb = 1;

#pragma unroll 1
    for (int tt = 1; tt < 16; tt++) {
        const float em0 = es[tt][0];
        const float esc = __expf(es[tt][jj] - em0);
        const float w = dot16(t, T0, T1, T2, T3) * esc;
        xW[pb][col][jj] = w;
        __syncwarp();
        const float w0 = xW[pb][col][0];
        const int   e  = ((__float_as_int(w0) >> 23) & 255) - 127;
        const float inv = __int_as_float((uint32_t)(127 - e) << 23);
        Lbase += em0; Lexp += e;
        const float4 u0 = *(const float4*)(xW[pb][col] + 0);
        const float4 u1 = *(const float4*)(xW[pb][col] + 4);
        const float4 u2 = *(const float4*)(xW[pb][col] + 8);
        const float4 u3 = *(const float4*)(xW[pb][col] + 12);
        t[0]=u0.x*inv; t[1]=u0.y*inv; t[2]=u0.z*inv; t[3]=u0.w*inv;
        t[4]=u1.x*inv; t[5]=u1.y*inv; t[6]=u1.z*inv; t[7]=u1.w*inv;
        t[8]=u2.x*inv; t[9]=u2.y*inv; t[10]=u2.z*inv; t[11]=u2.w*inv;
        t[12]=u3.x*inv; t[13]=u3.y*inv; t[14]=u3.z*inv; t[15]=u3.w*inv;
        w_own = w; inv_last = inv;
        if (tt == stash_tt)
            cmp[col][jj] = Lbase + (float)Lexp * LN2F + __logf(w_own * inv_last);
        pb ^= 1;
    }
    cm[col][jj] = Lbase + (float)Lexp * LN2F + __logf(w_own * inv_last);
    __syncthreads();

    if (c < NCHK && tid < 16) {
        float rm = cm[0][tid];
#pragma unroll
        for (int i = 1; i < 16; i++) rm = fmaxf(rm, cm[i][tid]);
        rms[tid] = rm;
    }
    if (need_partial && tid < 16) {
        float rm = cmp[0][tid];
#pragma unroll
        for (int i = 1; i < 16; i++) rm = fmaxf(rm, cmp[i][tid]);
        rmsp[tid] = rm;
    }
    __syncthreads();
    if (c < NCHK && tid < 16) {
        float gmax = rms[0];
#pragma unroll
        for (int i = 1; i < 16; i++) gmax = fmaxf(gmax, rms[i]);
        float o[16];
#pragma unroll
        for (int i = 0; i < 16; i++)
            o[i] = __expf(cm[i][tid] - gmax);
        float* dst = g_P + (size_t)(b * NCHK + c) * MS + tid * 16;
#pragma unroll
        for (int q = 0; q < 4; q++)
            *(float4*)(dst + q * 4) =
                make_float4(o[4*q], o[4*q+1], o[4*q+2], o[4*q+3]);
        if (tid == 0) g_R[b * NCHK + c] = gmax;
    }
    if (need_partial && tid < 16) {
        float gmax = rmsp[0];
#pragma unroll
        for (int i = 1; i < 16; i++) gmax = fmaxf(gmax, rmsp[i]);
        float o[16];
#pragma unroll
        for (int i = 0; i < 16; i++)
            o[i] = __expf(cmp[i][tid] - gmax);
        float* dst = g_Pp + (size_t)b * MS + tid * 16;
#pragma unroll
        for (int q = 0; q < 4; q++)
            *(float4*)(dst + q * 4) =
                make_float4(o[4*q], o[4*q+1], o[4*q+2], o[4*q+3]);
        if (tid == 0) g_Rp[b] = gmax;
    }
}

// ---------------------------------------------------------------------------
// Scan phase 2: binary-lifting.  Per batch: warp-parallel G2/G4/G8/G16
// products (<=5 sequential matmuls per warp, 4 barriers), then a chain of
// <=6 lse steps.  Gold path on warps 1-7.
// ---------------------------------------------------------------------------
// dynamic smem layout (floats):
#define OFF_C   0
#define OFF_G2  (31*MS)
#define OFF_G4  (OFF_G2 + 15*MS)
#define OFF_G8  (OFF_G4 + 7*MS)
#define OFF_G16 (OFF_G8 + 3*MS)
#define OFF_PP  (OFF_G16 + 1*MS)
#define P2_FLOATS (OFF_PP + MS)
#define P2_SMEM (P2_FLOATS * 4)      // 59392 B

__device__ __forceinline__ int clampe(int e) {
    return e < -60 ? -60 : (e > 60 ? 60 : e);
}

// warp product: D = Bm x A, scaled by 2^-(ea+eb); returns ea+eb
__device__ __forceinline__ int wprod16(const float* A, const float* Bm,
                                       float* D, int lane)
{
    const int ea = clampe(((__float_as_int(A[0])  >> 23) & 255) - 127);
    const int eb = clampe(((__float_as_int(Bm[0]) >> 23) & 255) - 127);
    const float inv = __int_as_float((uint32_t)(127 - ea - eb) << 23);
    const int j0 = lane >> 2;
    const int i0 = (lane & 3) * 4;
#pragma unroll
    for (int jo = 0; jo < 2; jo++) {
        const int j = j0 + jo * 8;
        float4 acc = make_float4(0.f, 0.f, 0.f, 0.f);
#pragma unroll
        for (int k = 0; k < 16; k++) {
            const float bv = Bm[j * 16 + k];
            const float4 av = *(const float4*)(A + k * 16 + i0);
            acc.x = fmaf(bv, av.x, acc.x);
            acc.y = fmaf(bv, av.y, acc.y);
            acc.z = fmaf(bv, av.z, acc.z);
            acc.w = fmaf(bv, av.w, acc.w);
        }
        *(float4*)(D + j * 16 + i0) =
            make_float4(acc.x * inv, acc.y * inv, acc.z * inv, acc.w * inv);
    }
    return ea + eb;
}

__global__ __launch_bounds__(256) void scan_p2(
    const float* __restrict__ trans, const int* __restrict__ lens,
    const int* __restrict__ tags, float* __restrict__ out)
{
    extern __shared__ float sm[];
    __shared__ float sR[NCHK];
    __shared__ float RG2[15], RG4[7], RG8[3], RG16[1];
    __shared__ float sOut;
    __shared__ float wsum[8];
    __shared__ __align__(16) float sA[16];
    __shared__ __align__(16) float sEa[16];

    const int b   = blockIdx.x;
    const int tid = threadIdx.x;
    const int wid = tid >> 5, lane = tid & 31;
    const int len   = lens[b];
    const int last  = len - 1;
    const int nfull = last >> 4;      // 15..31
    const int nrem  = last & 15;

    // ---- load all chunk matrices + partial + R scalars ----
    {
        const float4* src = (const float4*)(g_P + (size_t)b * NCHK * MS);
        float4* dst = (float4*)(sm + OFF_C);
        for (int u = tid; u < NCHK * (MS / 4); u += 256)
            dst[u] = src[u];
        if (tid < MS / 4)
            ((float4*)(sm + OFF_PP))[tid] = ((const float4*)(g_Pp + (size_t)b * MS))[tid];
        if (tid < NCHK) sR[tid] = g_R[b * NCHK + tid];
    }
    __syncthreads();

    // ---- phase A: 15 G2 products (warp w -> p = w, w+8) ----
#pragma unroll
    for (int rep = 0; rep < 2; rep++) {
        const int p = wid + rep * 8;
        if (p < 15) {
            const int esum = wprod16(sm + OFF_C + (2*p) * MS,
                                     sm + OFF_C + (2*p+1) * MS,
                                     sm + OFF_G2 + p * MS, lane);
            if (lane == 0)
                RG2[p] = sR[2*p] + sR[2*p+1] + (float)esum * LN2F;
        }
    }
    __syncthreads();

    // ---- phase B: 7 G4 products ----
    if (wid < 7) {
        const int p = wid;
        const int esum = wprod16(sm + OFF_G2 + (2*p) * MS,
                                 sm + OFF_G2 + (2*p+1) * MS,
                                 sm + OFF_G4 + p * MS, lane);
        if (lane == 0)
            RG4[p] = RG2[2*p] + RG2[2*p+1] + (float)esum * LN2F;
    }
    __syncthreads();

    // ---- phase C: 3 G8 products ----
    if (wid < 3) {
        const int p = wid;
        const int esum = wprod16(sm + OFF_G4 + (2*p) * MS,
                                 sm + OFF_G4 + (2*p+1) * MS,
                                 sm + OFF_G8 + p * MS, lane);
        if (lane == 0)
            RG8[p] = RG4[2*p] + RG4[2*p+1] + (float)esum * LN2F;
    }
    __syncthreads();

    // ---- phase D: 1 G16 product ----
    if (wid == 0) {
        const int esum = wprod16(sm + OFF_G8 + 0 * MS,
                                 sm + OFF_G8 + 1 * MS,
                                 sm + OFF_G16, lane);
        if (lane == 0)
            RG16[0] = RG8[0] + RG8[1] + (float)esum * LN2F;
    }
    __syncthreads();

    // ---- chain (warp 0, lanes 0-15) + gold (warps 1-7) ----
    if (wid == 0 && lane < 16) {
        const int jj = lane;
        float alpha = g_em[(size_t)b * KK_ + jj];

        auto lstep = [&](const float* P, float R) {
            sA[jj] = alpha;
            __syncwarp(0xffffu);
            const float m  = sA[0];
            const float ea = __expf(alpha - m);
            sEa[jj] = ea;
            __syncwarp(0xffffu);
            const float4 e0 = *(const float4*)(sEa + 0);
            const float4 e1 = *(const float4*)(sEa + 4);
            const float4 e2 = *(const float4*)(sEa + 8);
            const float4 e3 = *(const float4*)(sEa + 12);
            const float4 P0 = *(const float4*)(P + jj * 16 + 0);
            const float4 P1 = *(const float4*)(P + jj * 16 + 4);
            const float4 P2 = *(const float4*)(P + jj * 16 + 8);
            const float4 P3 = *(const float4*)(P + jj * 16 + 12);
            float s0 = e0.x*P0.x, s1 = e0.y*P0.y, s2 = e0.z*P0.z, s3 = e0.w*P0.w;
            s0 = fmaf(e1.x, P1.x, s0); s1 = fmaf(e1.y, P1.y, s1);
            s2 = fmaf(e1.z, P1.z, s2); s3 = fmaf(e1.w, P1.w, s3);
            s0 = fmaf(e2.x, P2.x, s0); s1 = fmaf(e2.y, P2.y, s1);
            s2 = fmaf(e2.z, P2.z, s2); s3 = fmaf(e2.w, P2.w, s3);
            s0 = fmaf(e3.x, P3.x, s0); s1 = fmaf(e3.y, P3.y, s1);
            s2 = fmaf(e3.z, P3.z, s2); s3 = fmaf(e3.w, P3.w, s3);
            alpha = m + __logf((s0 + s1) + (s2 + s3)) + R;
        };

        int pos = 0;
        if (nfull & 16) { lstep(sm + OFF_G16, RG16[0]); pos = 16; }
        if (nfull & 8)  { lstep(sm + OFF_G8 + (pos >> 3) * MS, RG8[pos >> 3]); pos += 8; }
        if (nfull & 4)  { lstep(sm + OFF_G4 + (pos >> 2) * MS, RG4[pos >> 2]); pos += 4; }
        if (nfull & 2)  { lstep(sm + OFF_G2 + (pos >> 1) * MS, RG2[pos >> 1]); pos += 2; }
        if (nfull & 1)  { lstep(sm + OFF_C + pos * MS, sR[pos]); pos += 1; }
        if (nrem)       { lstep(sm + OFF_PP, g_Rp[b]); }

        float m2 = alpha;
#pragma unroll
        for (int off = 8; off; off >>= 1)
            m2 = fmaxf(m2, __shfl_xor_sync(0xffffu, m2, off, 16));
        float ss = __expf(alpha - m2);
#pragma unroll
        for (int off = 8; off; off >>= 1)
            ss += __shfl_xor_sync(0xffffu, ss, off, 16);
        if (jj == 0) sOut = m2 + __logf(ss);
    } else if (wid >= 1) {
        const int gidx = tid - 32;     // 0..223
        float v = 0.f;
        for (int t = gidx; t < T_; t += 224) {
            if (t < len) {
                const int tag = tags[t * B_ + b];
                float x = g_em[(size_t)(t * B_ + b) * KK_ + tag];
                if (t > 0) x += trans[tag * KK_ + tags[(t - 1) * B_ + b]];
                v += x;
            }
        }
#pragma unroll
        for (int off = 16; off; off >>= 1)
            v += __shfl_xor_sync(0xffffffffu, v, off);
        if (lane == 0) wsum[wid] = v;
    }
    __syncthreads();
    if (tid == 0) {
        float gold = 0.f;
#pragma unroll
        for (int w = 1; w < 8; w++) gold += wsum[w];
        atomicAdd(out, sOut - gold);
    }
}

// ---------------------------------------------------------------------------
extern "C" void kernel_launch(void* const* d_in, const int* in_sizes, int n_in,
                              void* d_out, int out_size)
{
    (void)in_sizes; (void)n_in; (void)out_size;
    const float* hidden = (const float*)d_in[0];
    const float* W1     = (const float*)d_in[1];
    const float* b1     = (const float*)d_in[2];
    const float* W2     = (const float*)d_in[3];
    const float* b2     = (const float*)d_in[4];
    const float* trans  = (const float*)d_in[5];
    const int*   lens   = (const int*)d_in[6];
    const int*   tags   = (const int*)d_in[7];

    cudaFuncSetAttribute(gemm1_fused, cudaFuncAttributeMaxDynamicSharedMemorySize,
                         SMEM_BYTES);
    cudaFuncSetAttribute(scan_p2, cudaFuncAttributeMaxDynamicSharedMemorySize,
                         P2_SMEM);

    prep_kernel<<<PREP_TOTAL, 256>>>(hidden, W1, b2, (float*)d_out);
    gemm1_fused<<<dim3(H_ / BN, M_ / BM), 128, SMEM_BYTES>>>(b1, W2);
    scan_p1<<<dim3(NCHK + 1, B_), 256>>>(trans, lens);
    scan_p2<<<B_, 256, P2_SMEM>>>(trans, lens, tags, (float*)d_out);
}